// round 1
// baseline (speedup 1.0000x reference)
#include <cuda_runtime.h>
#include <cuda_bf16.h>
#include <math.h>

// ---------------- problem constants ----------------
#define S_TOK   2048
#define BATCH   16
#define HID     512      // H
#define HH      256      // Hh
#define NSENT   16
#define LW      128      // word seq len
#define NSEQW   256      // B*Nsent
#define MW      32768    // NSEQW*LW
#define G3      768      // 3*Hh

// ---------------- device scratch (no mallocs allowed) ----------------
__device__ float g_xpw[2UL * MW * G3];        // word input gates, per dir   (201MB)
__device__ float g_outw[(size_t)MW * HID];    // word BiGRU outputs          (67MB)
__device__ float g_uw[(size_t)MW * HID];      // word attn pre-tanh proj     (67MB)
__device__ float g_sent[NSEQW * HID];         // sentence vectors
__device__ float g_xps[2 * BATCH * NSENT * G3];
__device__ float g_outs[BATCH * NSENT * HID];
__device__ float g_us[BATCH * NSENT * HID];
__device__ float g_hw[2 * 2 * NSEQW * HH];    // [phase][dir][seq][j]
__device__ float g_hs[2 * 2 * BATCH * HH];    // sentence-level h

// ---------------- init: zero phase-0 hidden states ----------------
__global__ void zero_h_kernel() {
    int i = blockIdx.x * blockDim.x + threadIdx.x;
    if (i < 2 * NSEQW * HH) g_hw[i] = 0.f;
    if (i < 2 * BATCH * HH) g_hs[i] = 0.f;
}

// ---------------- SGEMM: C[m][n] = sum_k A[m][k]*W[n][k] + bias[n] ----------------
// 128x128 tile, BK=16, 256 threads, 8x8 register micro-tile.
// GATHER=true: A row m is token_feats[(tok*16 + b)*512], tok = m & 2047, b = m >> 11.
template<bool GATHER>
__global__ __launch_bounds__(256)
void sgemm_bias(const float* __restrict__ A,
                const float* __restrict__ tf,
                const float* __restrict__ W,
                const float* __restrict__ bias,
                float* __restrict__ C,
                int M, int N, int K)
{
    __shared__ __align__(16) float As[16][132];
    __shared__ __align__(16) float Bs[16][132];

    const int tid = threadIdx.x;
    const int tx = tid & 15;        // n direction
    const int ty = tid >> 4;        // m direction
    const int m0 = blockIdx.y * 128;
    const int n0 = blockIdx.x * 128;

    float acc[8][8];
#pragma unroll
    for (int i = 0; i < 8; i++)
#pragma unroll
        for (int j = 0; j < 8; j++) acc[i][j] = 0.f;

    for (int k0 = 0; k0 < K; k0 += 16) {
#pragma unroll
        for (int e = 0; e < 2; e++) {
            int idx = tid + e * 256;       // 0..511
            int r = idx >> 2;              // 0..127
            int q = idx & 3;               // 0..3
            // A tile
            const float* aptr;
            if (GATHER) {
                int gm = m0 + r;
                aptr = tf + ((size_t)((gm & 2047) * 16 + (gm >> 11))) * 512;
            } else {
                aptr = A + (size_t)(m0 + r) * K;
            }
            float4 av = *(const float4*)(aptr + k0 + q * 4);
            As[q * 4 + 0][r] = av.x;
            As[q * 4 + 1][r] = av.y;
            As[q * 4 + 2][r] = av.z;
            As[q * 4 + 3][r] = av.w;
            // B tile (W is N x K row-major)
            float4 bv = *(const float4*)(W + (size_t)(n0 + r) * K + k0 + q * 4);
            Bs[q * 4 + 0][r] = bv.x;
            Bs[q * 4 + 1][r] = bv.y;
            Bs[q * 4 + 2][r] = bv.z;
            Bs[q * 4 + 3][r] = bv.w;
        }
        __syncthreads();
#pragma unroll
        for (int kk = 0; kk < 16; kk++) {
            float4 a0 = *(const float4*)&As[kk][ty * 8];
            float4 a1 = *(const float4*)&As[kk][ty * 8 + 4];
            float4 b0 = *(const float4*)&Bs[kk][tx * 8];
            float4 b1 = *(const float4*)&Bs[kk][tx * 8 + 4];
            float av[8] = {a0.x, a0.y, a0.z, a0.w, a1.x, a1.y, a1.z, a1.w};
            float bv[8] = {b0.x, b0.y, b0.z, b0.w, b1.x, b1.y, b1.z, b1.w};
#pragma unroll
            for (int i = 0; i < 8; i++)
#pragma unroll
                for (int j = 0; j < 8; j++)
                    acc[i][j] = fmaf(av[i], bv[j], acc[i][j]);
        }
        __syncthreads();
    }

    float bj[8];
#pragma unroll
    for (int j = 0; j < 8; j++) bj[j] = bias[n0 + tx * 8 + j];
#pragma unroll
    for (int i = 0; i < 8; i++) {
        int gm = m0 + ty * 8 + i;
        float* crow = C + (size_t)gm * N + n0 + tx * 8;
        float4 o0, o1;
        o0.x = acc[i][0] + bj[0]; o0.y = acc[i][1] + bj[1];
        o0.z = acc[i][2] + bj[2]; o0.w = acc[i][3] + bj[3];
        o1.x = acc[i][4] + bj[4]; o1.y = acc[i][5] + bj[5];
        o1.z = acc[i][6] + bj[6]; o1.w = acc[i][7] + bj[7];
        *(float4*)(crow) = o0;
        *(float4*)(crow + 4) = o1;
    }
}

// ---------------- GRU step ----------------
// grid: (8 j-groups of 32, nseq/SPB seq-groups, 2 dirs); 256 threads = 32 jj x 8 sl.
// Each thread: 3 gate dots (len 256) for SPB/8 sequences. W rows + h tile in shared
// (stride 257 -> conflict-free W reads, broadcast h reads).
template<int SPB>
__global__ __launch_bounds__(256)
void gru_step(const float* __restrict__ xp_base,   // [2][nseq*T*768]
              const float* __restrict__ whh_f, const float* __restrict__ whh_b,
              const float* __restrict__ bhh_f, const float* __restrict__ bhh_b,
              const float* __restrict__ hin_base,  // [2][nseq*256]
              float* __restrict__ hout_base,
              float* __restrict__ outbuf,          // [nseq*T*512]
              int nseq, int T, int step)
{
    extern __shared__ float sm[];
    float* Ws = sm;                    // 96 rows, stride 257
    float* hs = sm + 96 * 257;         // SPB rows, stride 257

    const int dir = blockIdx.z;
    const float* whh = dir ? whh_b : whh_f;
    const float* bhh = dir ? bhh_b : bhh_f;
    const float* xp  = xp_base + (size_t)dir * nseq * T * G3;
    const float* hin = hin_base + (size_t)dir * nseq * HH;
    float* hout      = hout_base + (size_t)dir * nseq * HH;
    const int tt = dir ? (T - 1 - step) : step;
    const int j0 = blockIdx.x * 32;
    const int sg0 = blockIdx.y * SPB;
    const int tid = threadIdx.x;

    // stage 96 W_hh rows (gates r,z,n for j in [j0, j0+32))
    for (int i = tid; i < 96 * 64; i += 256) {
        int r = i >> 6, c = (i & 63) * 4;
        int gate = r >> 5, jj = r & 31;
        float4 v = *(const float4*)(whh + ((size_t)(gate * 256 + j0 + jj)) * 256 + c);
        float* d = Ws + r * 257 + c;
        d[0] = v.x; d[1] = v.y; d[2] = v.z; d[3] = v.w;
    }
    // stage h tile
    for (int i = tid; i < SPB * 64; i += 256) {
        int r = i >> 6, c = (i & 63) * 4;
        float4 v = *(const float4*)(hin + (size_t)(sg0 + r) * 256 + c);
        float* d = hs + r * 257 + c;
        d[0] = v.x; d[1] = v.y; d[2] = v.z; d[3] = v.w;
    }
    __syncthreads();

    const int NS = SPB / 8;
    const int jj = tid & 31, sl = tid >> 5;
    float aR[NS], aZ[NS], aN[NS];
#pragma unroll
    for (int n = 0; n < NS; n++) { aR[n] = 0.f; aZ[n] = 0.f; aN[n] = 0.f; }

    const float* wr = Ws + jj * 257;
    const float* wz = Ws + (32 + jj) * 257;
    const float* wn = Ws + (64 + jj) * 257;
#pragma unroll 4
    for (int k = 0; k < 256; k++) {
        float wrv = wr[k], wzv = wz[k], wnv = wn[k];
#pragma unroll
        for (int n = 0; n < NS; n++) {
            float hv = hs[(sl + n * 8) * 257 + k];
            aR[n] = fmaf(wrv, hv, aR[n]);
            aZ[n] = fmaf(wzv, hv, aZ[n]);
            aN[n] = fmaf(wnv, hv, aN[n]);
        }
    }

    const int j = j0 + jj;
    const float br = bhh[j], bz = bhh[256 + j], bn = bhh[512 + j];
#pragma unroll
    for (int n = 0; n < NS; n++) {
        int s = sg0 + sl + n * 8;
        const float* xr = xp + ((size_t)s * T + tt) * G3;
        float r  = 1.f / (1.f + expf(-(xr[j]       + aR[n] + br)));
        float z  = 1.f / (1.f + expf(-(xr[256 + j] + aZ[n] + bz)));
        float nn = tanhf(xr[512 + j] + r * (aN[n] + bn));
        float hold = hs[(sl + n * 8) * 257 + j];
        float hnew = (1.f - z) * nn + z * hold;
        hout[(size_t)s * HH + j] = hnew;
        outbuf[((size_t)s * T + tt) * HID + dir * HH + j] = hnew;
    }
}

// ---------------- attention: scores(tanh(u)·ctx) -> softmax_t -> weighted sum ----------------
__global__ __launch_bounds__(256)
void attn_reduce(const float* __restrict__ u,      // [R*T*512] pre-tanh proj (+bias)
                 const float* __restrict__ feats,  // [R*T*512]
                 const float* __restrict__ ctx,    // [512]
                 float* __restrict__ dst,          // [R*512]
                 int T)
{
    const int seq = blockIdx.x;
    const int tid = threadIdx.x;
    __shared__ float sctx[512];
    __shared__ float ssc[128];
    __shared__ float sred[256];

    for (int g = tid; g < 512; g += 256) sctx[g] = ctx[g];
    __syncthreads();

    const int lane = tid & 31, warp = tid >> 5;
    for (int t = warp; t < T; t += 8) {
        const float* ur = u + ((size_t)seq * T + t) * 512;
        float p = 0.f;
        for (int g = lane; g < 512; g += 32) p += tanhf(ur[g]) * sctx[g];
#pragma unroll
        for (int o = 16; o; o >>= 1) p += __shfl_down_sync(0xffffffffu, p, o);
        if (lane == 0) ssc[t] = p;
    }
    __syncthreads();

    // softmax over T (T <= 128)
    float v = (tid < T) ? ssc[tid] : -1e30f;
    sred[tid] = v; __syncthreads();
    for (int o = 128; o; o >>= 1) { if (tid < o) sred[tid] = fmaxf(sred[tid], sred[tid + o]); __syncthreads(); }
    float mx = sred[0]; __syncthreads();
    float e = (tid < T) ? expf(v - mx) : 0.f;
    sred[tid] = e; __syncthreads();
    for (int o = 128; o; o >>= 1) { if (tid < o) sred[tid] += sred[tid + o]; __syncthreads(); }
    float inv = 1.f / sred[0]; __syncthreads();
    if (tid < T) ssc[tid] = e * inv;
    __syncthreads();

    for (int h = tid; h < 512; h += 256) {
        float acc = 0.f;
        for (int t = 0; t < T; t++)
            acc = fmaf(ssc[t], feats[((size_t)seq * T + t) * 512 + h], acc);
        dst[(size_t)seq * 512 + h] = acc;
    }
}

// ---------------- host ----------------
extern "C" void kernel_launch(void* const* d_in, const int* in_sizes, int n_in,
                              void* d_out, int out_size)
{
    const float* tf       = (const float*)d_in[0];
    // d_in[1] = sentence_spans (uniform; index math used instead)
    const float* w_wih_f  = (const float*)d_in[2];
    const float* w_whh_f  = (const float*)d_in[3];
    const float* w_bih_f  = (const float*)d_in[4];
    const float* w_bhh_f  = (const float*)d_in[5];
    const float* w_wih_b  = (const float*)d_in[6];
    const float* w_whh_b  = (const float*)d_in[7];
    const float* w_bih_b  = (const float*)d_in[8];
    const float* w_bhh_b  = (const float*)d_in[9];
    const float* s_wih_f  = (const float*)d_in[10];
    const float* s_whh_f  = (const float*)d_in[11];
    const float* s_bih_f  = (const float*)d_in[12];
    const float* s_bhh_f  = (const float*)d_in[13];
    const float* s_wih_b  = (const float*)d_in[14];
    const float* s_whh_b  = (const float*)d_in[15];
    const float* s_bih_b  = (const float*)d_in[16];
    const float* s_bhh_b  = (const float*)d_in[17];
    const float* w_attn_w = (const float*)d_in[18];
    const float* w_attn_b = (const float*)d_in[19];
    const float* w_ctx    = (const float*)d_in[20];
    const float* s_attn_w = (const float*)d_in[21];
    const float* s_attn_b = (const float*)d_in[22];
    const float* s_ctx    = (const float*)d_in[23];

    float *xpw, *outw, *uw, *sent, *xps, *outs, *us, *hw, *hs;
    cudaGetSymbolAddress((void**)&xpw,  g_xpw);
    cudaGetSymbolAddress((void**)&outw, g_outw);
    cudaGetSymbolAddress((void**)&uw,   g_uw);
    cudaGetSymbolAddress((void**)&sent, g_sent);
    cudaGetSymbolAddress((void**)&xps,  g_xps);
    cudaGetSymbolAddress((void**)&outs, g_outs);
    cudaGetSymbolAddress((void**)&us,   g_us);
    cudaGetSymbolAddress((void**)&hw,   g_hw);
    cudaGetSymbolAddress((void**)&hs,   g_hs);

    const size_t smw = (96 + 32) * 257 * sizeof(float);   // 131,584 B
    const size_t sms = (96 + 16) * 257 * sizeof(float);   // 115,136 B
    cudaFuncSetAttribute(gru_step<32>, cudaFuncAttributeMaxDynamicSharedMemorySize, (int)smw);
    cudaFuncSetAttribute(gru_step<16>, cudaFuncAttributeMaxDynamicSharedMemorySize, (int)sms);

    // 0) zero hidden-state phase 0
    zero_h_kernel<<<(2 * NSEQW * HH + 255) / 256, 256>>>();

    // 1) word input-gate GEMMs (gathered directly from token_feats)
    {
        dim3 g(G3 / 128, MW / 128);   // (6, 256)
        sgemm_bias<true><<<g, 256>>>(nullptr, tf, w_wih_f, w_bih_f, xpw, MW, G3, HID);
        sgemm_bias<true><<<g, 256>>>(nullptr, tf, w_wih_b, w_bih_b,
                                     xpw + (size_t)MW * G3, MW, G3, HID);
    }

    // 2) word BiGRU recurrence: 128 per-step launches, ping-pong h
    for (int s = 0; s < LW; s++) {
        dim3 g(8, NSEQW / 32, 2);     // (8, 8, 2)
        gru_step<32><<<g, 256, smw>>>(xpw, w_whh_f, w_whh_b, w_bhh_f, w_bhh_b,
                                      hw + (size_t)(s & 1) * 2 * NSEQW * HH,
                                      hw + (size_t)((s + 1) & 1) * 2 * NSEQW * HH,
                                      outw, NSEQW, LW, s);
    }

    // 3) word attention: projection GEMM + fused reduce -> sentence vectors
    {
        dim3 g(HID / 128, MW / 128);  // (4, 256)
        sgemm_bias<false><<<g, 256>>>(outw, nullptr, w_attn_w, w_attn_b, uw, MW, HID, HID);
        attn_reduce<<<NSEQW, 256>>>(uw, outw, w_ctx, sent, LW);
    }

    // 4) sentence input-gate GEMMs
    {
        dim3 g(G3 / 128, (BATCH * NSENT) / 128);  // (6, 2)
        sgemm_bias<false><<<g, 256>>>(sent, nullptr, s_wih_f, s_bih_f, xps,
                                      BATCH * NSENT, G3, HID);
        sgemm_bias<false><<<g, 256>>>(sent, nullptr, s_wih_b, s_bih_b,
                                      xps + (size_t)BATCH * NSENT * G3,
                                      BATCH * NSENT, G3, HID);
    }

    // 5) sentence BiGRU: 16 per-step launches
    for (int s = 0; s < NSENT; s++) {
        dim3 g(8, 1, 2);
        gru_step<16><<<g, 256, sms>>>(xps, s_whh_f, s_whh_b, s_bhh_f, s_bhh_b,
                                      hs + (size_t)(s & 1) * 2 * BATCH * HH,
                                      hs + (size_t)((s + 1) & 1) * 2 * BATCH * HH,
                                      outs, BATCH, NSENT, s);
    }

    // 6) sentence attention -> output (B, 512) fp32
    {
        dim3 g(HID / 128, (BATCH * NSENT) / 128);  // (4, 2)
        sgemm_bias<false><<<g, 256>>>(outs, nullptr, s_attn_w, s_attn_b, us,
                                      BATCH * NSENT, HID, HID);
        attn_reduce<<<BATCH, 256>>>(us, outs, s_ctx, (float*)d_out, NSENT);
    }
}

// round 2
// speedup vs baseline: 1.3542x; 1.3542x over previous
#include <cuda_runtime.h>
#include <cuda_bf16.h>
#include <math.h>

// ---------------- problem constants ----------------
#define HID     512      // H
#define HH      256      // Hh
#define G3      768      // 3*Hh
#define BATCH   16
#define NSENT   16
#define LW      128      // word seq len
#define NSEQW   256      // B*Nsent
#define MW      32768    // NSEQW*LW

// ---------------- device scratch (no mallocs allowed) ----------------
__device__ float g_xpw[2UL * MW * G3];        // word input gates, per dir
__device__ float g_outw[(size_t)MW * HID];    // word BiGRU outputs
__device__ float g_uw[(size_t)MW * HID];      // word attn pre-tanh proj
__device__ float g_sent[NSEQW * HID];         // sentence vectors
__device__ float g_xps[2 * BATCH * NSENT * G3];
__device__ float g_outs[BATCH * NSENT * HID];
__device__ float g_us[BATCH * NSENT * HID];
// h ping-pong, layout [phase][dir][j(256)][seq]   (j-major for coalescing)
__device__ float g_hw[2 * 2 * HH * NSEQW];
__device__ float g_hs[2 * 2 * HH * BATCH];
// software grid barriers (zero-initialized; cnt self-resets, sense is monotonic)
__device__ unsigned g_barw_cnt, g_barw_sense;
__device__ unsigned g_bars_cnt, g_bars_sense;

// ---------------- barrier helpers ----------------
__device__ __forceinline__ unsigned ld_acq(const unsigned* p) {
    unsigned v;
    asm volatile("ld.acquire.gpu.u32 %0, [%1];" : "=r"(v) : "l"(p) : "memory");
    return v;
}

__device__ __forceinline__ void grid_barrier(unsigned* cnt, unsigned* sense,
                                             unsigned target, int total) {
    __syncthreads();
    if (threadIdx.x == 0) {
        __threadfence();
        unsigned t = atomicAdd(cnt, 1u);
        if (t == (unsigned)(total - 1)) {
            *cnt = 0u;  // all arrived; reset before release
            asm volatile("red.release.gpu.add.u32 [%0], 1;" :: "l"(sense) : "memory");
        } else {
            while (ld_acq(sense) != target) { }
        }
    }
    __syncthreads();
}

// ---------------- SGEMM: C[m][n] = sum_k A[m][k]*W[n][k] + bias[n] ----------------
// 128x128 tile, BK=16, 256 threads, 8x8 register micro-tile.
// GATHER=true: A row m is token_feats[(tok*16 + b)*512], tok = m & 2047, b = m >> 11.
template<bool GATHER>
__global__ __launch_bounds__(256)
void sgemm_bias(const float* __restrict__ A,
                const float* __restrict__ tf,
                const float* __restrict__ W,
                const float* __restrict__ bias,
                float* __restrict__ C,
                int M, int N, int K)
{
    __shared__ __align__(16) float As[16][132];
    __shared__ __align__(16) float Bs[16][132];

    const int tid = threadIdx.x;
    const int tx = tid & 15;
    const int ty = tid >> 4;
    const int m0 = blockIdx.y * 128;
    const int n0 = blockIdx.x * 128;

    float acc[8][8];
#pragma unroll
    for (int i = 0; i < 8; i++)
#pragma unroll
        for (int j = 0; j < 8; j++) acc[i][j] = 0.f;

    for (int k0 = 0; k0 < K; k0 += 16) {
#pragma unroll
        for (int e = 0; e < 2; e++) {
            int idx = tid + e * 256;
            int r = idx >> 2;
            int q = idx & 3;
            const float* aptr;
            if (GATHER) {
                int gm = m0 + r;
                aptr = tf + ((size_t)((gm & 2047) * 16 + (gm >> 11))) * 512;
            } else {
                aptr = A + (size_t)(m0 + r) * K;
            }
            float4 av = *(const float4*)(aptr + k0 + q * 4);
            As[q * 4 + 0][r] = av.x;
            As[q * 4 + 1][r] = av.y;
            As[q * 4 + 2][r] = av.z;
            As[q * 4 + 3][r] = av.w;
            float4 bv = *(const float4*)(W + (size_t)(n0 + r) * K + k0 + q * 4);
            Bs[q * 4 + 0][r] = bv.x;
            Bs[q * 4 + 1][r] = bv.y;
            Bs[q * 4 + 2][r] = bv.z;
            Bs[q * 4 + 3][r] = bv.w;
        }
        __syncthreads();
#pragma unroll
        for (int kk = 0; kk < 16; kk++) {
            float4 a0 = *(const float4*)&As[kk][ty * 8];
            float4 a1 = *(const float4*)&As[kk][ty * 8 + 4];
            float4 b0 = *(const float4*)&Bs[kk][tx * 8];
            float4 b1 = *(const float4*)&Bs[kk][tx * 8 + 4];
            float av[8] = {a0.x, a0.y, a0.z, a0.w, a1.x, a1.y, a1.z, a1.w};
            float bv[8] = {b0.x, b0.y, b0.z, b0.w, b1.x, b1.y, b1.z, b1.w};
#pragma unroll
            for (int i = 0; i < 8; i++)
#pragma unroll
                for (int j = 0; j < 8; j++)
                    acc[i][j] = fmaf(av[i], bv[j], acc[i][j]);
        }
        __syncthreads();
    }

    float bj[8];
#pragma unroll
    for (int j = 0; j < 8; j++) bj[j] = bias[n0 + tx * 8 + j];
#pragma unroll
    for (int i = 0; i < 8; i++) {
        int gm = m0 + ty * 8 + i;
        float* crow = C + (size_t)gm * N + n0 + tx * 8;
        float4 o0, o1;
        o0.x = acc[i][0] + bj[0]; o0.y = acc[i][1] + bj[1];
        o0.z = acc[i][2] + bj[2]; o0.w = acc[i][3] + bj[3];
        o1.x = acc[i][4] + bj[4]; o1.y = acc[i][5] + bj[5];
        o1.z = acc[i][6] + bj[6]; o1.w = acc[i][7] + bj[7];
        *(float4*)(crow) = o0;
        *(float4*)(crow + 4) = o1;
    }
}

// ---------------- persistent GRU recurrence ----------------
// grid: (8 j-groups, nseq/SPB seq-groups, 2 dirs). 256 thr = 32 jj x 8 sl.
// W_hh (96 rows x 256) staged in smem ONCE. h ping-pongs through L2 in
// [dir][j][seq] layout. Inner loop uses packed fma.rn.f32x2 over seq-pairs:
// h pairs loaded directly as ld.shared.b64 from an interleaved k-major tile.
template<int T, int SPB>
__global__ void __launch_bounds__(256, 1)
gru_persistent(const float* __restrict__ xp_base,   // [2][nseq*T*768]
               const float* __restrict__ whh_f, const float* __restrict__ whh_b,
               const float* __restrict__ bhh_f, const float* __restrict__ bhh_b,
               float* __restrict__ hbuf,            // [2][2][256][nseq]
               float* __restrict__ outbuf,          // [nseq*T*512]
               unsigned* bar_cnt, unsigned* bar_sense,
               int nseq, int total)
{
    constexpr int NP = SPB / 16;           // seq-pairs per thread
    extern __shared__ float sm[];
    float* Ws  = sm;                       // 96 x 257
    float* hsm = sm + 96 * 257;            // [k(256)][SPB] seq-interleaved
    float* xs  = hsm + 256 * SPB;          // 32 x (SPB+1) transpose buffer

    const int tid = threadIdx.x;
    const int jj = tid & 31, sl = tid >> 5;
    const int j0 = blockIdx.x * 32;
    const int sg0 = blockIdx.y * SPB;
    const int dir = blockIdx.z;
    const float* whh = dir ? whh_b : whh_f;
    const float* bhh = dir ? bhh_b : bhh_f;
    const float* xp  = xp_base + (size_t)dir * nseq * T * G3;

    // stage W_hh rows for gates r,z,n, j in [j0, j0+32)  — once
    for (int i = tid; i < 96 * 64; i += 256) {
        int r = i >> 6, c = (i & 63) * 4;
        int gate = r >> 5, jr = r & 31;
        float4 v = *(const float4*)(whh + ((size_t)(gate * 256 + j0 + jr)) * 256 + c);
        float* d = Ws + r * 257 + c;
        d[0] = v.x; d[1] = v.y; d[2] = v.z; d[3] = v.w;
    }

    const int j = j0 + jj;
    const float br = bhh[j], bz = bhh[256 + j], bn = bhh[512 + j];
    const unsigned base = ld_acq(bar_sense);   // before any block can bump it
    __syncthreads();

    for (int step = 0; step < T; step++) {
        const int tt = dir ? (T - 1 - step) : step;

        // prefetch input-gate terms (hides L2/DRAM latency behind staging+loop)
        float xr_[2 * NP], xz_[2 * NP], xn_[2 * NP];
#pragma unroll
        for (int n = 0; n < NP; n++)
#pragma unroll
            for (int e = 0; e < 2; e++) {
                int sL = (sl + n * 8) * 2 + e;
                const float* row = xp + ((size_t)(sg0 + sL) * T + tt) * G3;
                xr_[n * 2 + e] = row[j];
                xz_[n * 2 + e] = row[256 + j];
                xn_[n * 2 + e] = row[512 + j];
            }

        // stage h(t): coalesced LDG (j-major global), conflict-free STS
        const float* hcur = hbuf + ((size_t)(step & 1) * 2 + dir) * ((size_t)HH * nseq);
        if (step == 0) {
            for (int i = tid; i < 256 * SPB; i += 256) hsm[i] = 0.f;
        } else {
            for (int i = tid; i < 256 * SPB; i += 256) {
                int k = i / SPB, s = i - k * SPB;
                hsm[i] = hcur[(size_t)k * nseq + sg0 + s];
            }
        }
        __syncthreads();

        unsigned long long aR[NP], aZ[NP], aN[NP];
#pragma unroll
        for (int n = 0; n < NP; n++) { aR[n] = 0ULL; aZ[n] = 0ULL; aN[n] = 0ULL; }

        const float* wr = Ws + jj * 257;
        const float* wz = wr + 32 * 257;
        const float* wn = wr + 64 * 257;
#pragma unroll 8
        for (int k = 0; k < 256; k++) {
            unsigned long long r2, z2, n2;
            float fr = wr[k], fz = wz[k], fn = wn[k];
            asm("mov.b64 %0, {%1, %1};" : "=l"(r2) : "f"(fr));
            asm("mov.b64 %0, {%1, %1};" : "=l"(z2) : "f"(fz));
            asm("mov.b64 %0, {%1, %1};" : "=l"(n2) : "f"(fn));
#pragma unroll
            for (int n = 0; n < NP; n++) {
                unsigned long long h2 =
                    *(const unsigned long long*)(hsm + k * SPB + (sl + n * 8) * 2);
                asm("fma.rn.f32x2 %0, %1, %2, %0;" : "+l"(aR[n]) : "l"(r2), "l"(h2));
                asm("fma.rn.f32x2 %0, %1, %2, %0;" : "+l"(aZ[n]) : "l"(z2), "l"(h2));
                asm("fma.rn.f32x2 %0, %1, %2, %0;" : "+l"(aN[n]) : "l"(n2), "l"(h2));
            }
        }

        // gates + h update
#pragma unroll
        for (int n = 0; n < NP; n++) {
            float rv[2], zv[2], nv[2];
            asm("mov.b64 {%0, %1}, %2;" : "=f"(rv[0]), "=f"(rv[1]) : "l"(aR[n]));
            asm("mov.b64 {%0, %1}, %2;" : "=f"(zv[0]), "=f"(zv[1]) : "l"(aZ[n]));
            asm("mov.b64 {%0, %1}, %2;" : "=f"(nv[0]), "=f"(nv[1]) : "l"(aN[n]));
#pragma unroll
            for (int e = 0; e < 2; e++) {
                int sL = (sl + n * 8) * 2 + e;
                float hold = hsm[(size_t)j * SPB + sL];
                float r  = 1.f / (1.f + expf(-(xr_[n * 2 + e] + rv[e] + br)));
                float z  = 1.f / (1.f + expf(-(xz_[n * 2 + e] + zv[e] + bz)));
                float nn = tanhf(xn_[n * 2 + e] + r * (nv[e] + bn));
                float hnew = (1.f - z) * nn + z * hold;
                xs[jj * (SPB + 1) + sL] = hnew;
                outbuf[((size_t)(sg0 + sL) * T + tt) * HID + dir * HH + j] = hnew;
            }
        }
        __syncthreads();

        // transposed, coalesced h(t+1) write-out
        float* hnext = hbuf + ((size_t)((step + 1) & 1) * 2 + dir) * ((size_t)HH * nseq);
#pragma unroll
        for (int q = 0; q < 4; q++) {
            int jr = sl * 4 + q;
            if (jj < SPB)
                hnext[(size_t)(j0 + jr) * nseq + sg0 + jj] = xs[jr * (SPB + 1) + jj];
        }

        if (step < T - 1)
            grid_barrier(bar_cnt, bar_sense, base + (unsigned)step + 1u, total);
    }
}

// ---------------- attention: scores(tanh(u)·ctx) -> softmax_t -> weighted sum ----------------
__global__ __launch_bounds__(256)
void attn_reduce(const float* __restrict__ u,
                 const float* __restrict__ feats,
                 const float* __restrict__ ctx,
                 float* __restrict__ dst,
                 int T)
{
    const int seq = blockIdx.x;
    const int tid = threadIdx.x;
    __shared__ float sctx[512];
    __shared__ float ssc[128];
    __shared__ float sred[256];

    for (int g = tid; g < 512; g += 256) sctx[g] = ctx[g];
    __syncthreads();

    const int lane = tid & 31, warp = tid >> 5;
    for (int t = warp; t < T; t += 8) {
        const float* ur = u + ((size_t)seq * T + t) * 512;
        float p = 0.f;
        for (int g = lane; g < 512; g += 32) p += tanhf(ur[g]) * sctx[g];
#pragma unroll
        for (int o = 16; o; o >>= 1) p += __shfl_down_sync(0xffffffffu, p, o);
        if (lane == 0) ssc[t] = p;
    }
    __syncthreads();

    float v = (tid < T) ? ssc[tid] : -1e30f;
    sred[tid] = v; __syncthreads();
    for (int o = 128; o; o >>= 1) { if (tid < o) sred[tid] = fmaxf(sred[tid], sred[tid + o]); __syncthreads(); }
    float mx = sred[0]; __syncthreads();
    float e = (tid < T) ? expf(v - mx) : 0.f;
    sred[tid] = e; __syncthreads();
    for (int o = 128; o; o >>= 1) { if (tid < o) sred[tid] += sred[tid + o]; __syncthreads(); }
    float inv = 1.f / sred[0]; __syncthreads();
    if (tid < T) ssc[tid] = e * inv;
    __syncthreads();

    for (int h = tid; h < 512; h += 256) {
        float acc = 0.f;
        for (int t = 0; t < T; t++)
            acc = fmaf(ssc[t], feats[((size_t)seq * T + t) * 512 + h], acc);
        dst[(size_t)seq * 512 + h] = acc;
    }
}

// ---------------- host ----------------
extern "C" void kernel_launch(void* const* d_in, const int* in_sizes, int n_in,
                              void* d_out, int out_size)
{
    const float* tf       = (const float*)d_in[0];
    const float* w_wih_f  = (const float*)d_in[2];
    const float* w_whh_f  = (const float*)d_in[3];
    const float* w_bih_f  = (const float*)d_in[4];
    const float* w_bhh_f  = (const float*)d_in[5];
    const float* w_wih_b  = (const float*)d_in[6];
    const float* w_whh_b  = (const float*)d_in[7];
    const float* w_bih_b  = (const float*)d_in[8];
    const float* w_bhh_b  = (const float*)d_in[9];
    const float* s_wih_f  = (const float*)d_in[10];
    const float* s_whh_f  = (const float*)d_in[11];
    const float* s_bih_f  = (const float*)d_in[12];
    const float* s_bhh_f  = (const float*)d_in[13];
    const float* s_wih_b  = (const float*)d_in[14];
    const float* s_whh_b  = (const float*)d_in[15];
    const float* s_bih_b  = (const float*)d_in[16];
    const float* s_bhh_b  = (const float*)d_in[17];
    const float* w_attn_w = (const float*)d_in[18];
    const float* w_attn_b = (const float*)d_in[19];
    const float* w_ctx    = (const float*)d_in[20];
    const float* s_attn_w = (const float*)d_in[21];
    const float* s_attn_b = (const float*)d_in[22];
    const float* s_ctx    = (const float*)d_in[23];

    float *xpw, *outw, *uw, *sent, *xps, *outs, *us, *hw, *hs;
    unsigned *bwc, *bws, *bsc, *bss;
    cudaGetSymbolAddress((void**)&xpw,  g_xpw);
    cudaGetSymbolAddress((void**)&outw, g_outw);
    cudaGetSymbolAddress((void**)&uw,   g_uw);
    cudaGetSymbolAddress((void**)&sent, g_sent);
    cudaGetSymbolAddress((void**)&xps,  g_xps);
    cudaGetSymbolAddress((void**)&outs, g_outs);
    cudaGetSymbolAddress((void**)&us,   g_us);
    cudaGetSymbolAddress((void**)&hw,   g_hw);
    cudaGetSymbolAddress((void**)&hs,   g_hs);
    cudaGetSymbolAddress((void**)&bwc,  g_barw_cnt);
    cudaGetSymbolAddress((void**)&bws,  g_barw_sense);
    cudaGetSymbolAddress((void**)&bsc,  g_bars_cnt);
    cudaGetSymbolAddress((void**)&bss,  g_bars_sense);

    const size_t smw = (96 * 257 + 256 * 32 + 32 * 33) * sizeof(float);  // 135,680 B
    const size_t sms = (96 * 257 + 256 * 16 + 32 * 17) * sizeof(float);  // 117,248 B
    cudaFuncSetAttribute(gru_persistent<LW, 32>,
                         cudaFuncAttributeMaxDynamicSharedMemorySize, (int)smw);
    cudaFuncSetAttribute(gru_persistent<NSENT, 16>,
                         cudaFuncAttributeMaxDynamicSharedMemorySize, (int)sms);

    // 1) word input-gate GEMMs (gathered directly from token_feats)
    {
        dim3 g(G3 / 128, MW / 128);
        sgemm_bias<true><<<g, 256>>>(nullptr, tf, w_wih_f, w_bih_f, xpw, MW, G3, HID);
        sgemm_bias<true><<<g, 256>>>(nullptr, tf, w_wih_b, w_bih_b,
                                     xpw + (size_t)MW * G3, MW, G3, HID);
    }

    // 2) word BiGRU recurrence: ONE persistent launch (128 co-resident blocks)
    {
        dim3 g(8, NSEQW / 32, 2);   // 128 blocks
        gru_persistent<LW, 32><<<g, 256, smw>>>(xpw, w_whh_f, w_whh_b, w_bhh_f, w_bhh_b,
                                                hw, outw, bwc, bws, NSEQW, 128);
    }

    // 3) word attention: projection GEMM + fused reduce -> sentence vectors
    {
        dim3 g(HID / 128, MW / 128);
        sgemm_bias<false><<<g, 256>>>(outw, nullptr, w_attn_w, w_attn_b, uw, MW, HID, HID);
        attn_reduce<<<NSEQW, 256>>>(uw, outw, w_ctx, sent, LW);
    }

    // 4) sentence input-gate GEMMs
    {
        dim3 g(G3 / 128, (BATCH * NSENT) / 128);
        sgemm_bias<false><<<g, 256>>>(sent, nullptr, s_wih_f, s_bih_f, xps,
                                      BATCH * NSENT, G3, HID);
        sgemm_bias<false><<<g, 256>>>(sent, nullptr, s_wih_b, s_bih_b,
                                      xps + (size_t)BATCH * NSENT * G3,
                                      BATCH * NSENT, G3, HID);
    }

    // 5) sentence BiGRU: ONE persistent launch (16 blocks)
    {
        dim3 g(8, 1, 2);
        gru_persistent<NSENT, 16><<<g, 256, sms>>>(xps, s_whh_f, s_whh_b, s_bhh_f, s_bhh_b,
                                                   hs, outs, bsc, bss, BATCH, 16);
    }

    // 6) sentence attention -> output (B, 512) fp32
    {
        dim3 g(HID / 128, (BATCH * NSENT) / 128);
        sgemm_bias<false><<<g, 256>>>(outs, nullptr, s_attn_w, s_attn_b, us,
                                      BATCH * NSENT, HID, HID);
        attn_reduce<<<BATCH, 256>>>(us, outs, s_ctx, (float*)d_out, NSENT);
    }
}

// round 4
// speedup vs baseline: 2.0338x; 1.5019x over previous
#include <cuda_runtime.h>
#include <cuda_bf16.h>
#include <math.h>
#include <stdint.h>

// ---------------- problem constants ----------------
#define HID     512      // H
#define HH      256      // Hh
#define G3      768      // 3*Hh
#define BATCH   16
#define NSENT   16
#define LW      128      // word seq len
#define NSEQW   256      // B*Nsent
#define MW      32768    // NSEQW*LW
#define WSLOT   (768 * 512)

// ---------------- device scratch (no mallocs allowed) ----------------
__device__ float g_xpw[2UL * MW * G3];        // word input gates, per dir
__device__ float g_outw[(size_t)MW * HID];    // word BiGRU outputs
__device__ float g_uw[(size_t)MW * HID];      // word attn pre-tanh proj
__device__ float g_sent[NSEQW * HID];         // sentence vectors
__device__ float g_xps[2 * BATCH * NSENT * G3];
__device__ float g_outs[BATCH * NSENT * HID];
__device__ float g_us[BATCH * NSENT * HID];
__device__ float g_hw[2 * 2 * HH * NSEQW];    // h ping-pong [phase][dir][j][seq]
__device__ float g_hs[2 * 2 * HH * BATCH];
__device__ unsigned g_barw_cnt[16], g_barw_sense[16];   // 16 groups of 8 blocks
__device__ unsigned g_bars_cnt[2],  g_bars_sense[2];
// bf16 split planes
__device__ __nv_bfloat16 g_Ahi[(size_t)MW * HID];
__device__ __nv_bfloat16 g_Alo[(size_t)MW * HID];
__device__ __nv_bfloat16 g_Whi[6 * WSLOT];
__device__ __nv_bfloat16 g_Wlo[6 * WSLOT];

// ---------------- helpers ----------------
__device__ __forceinline__ uint32_t smem_u32(const void* p) {
    uint32_t a;
    asm("{ .reg .u64 t; cvta.to.shared.u64 t, %1; cvt.u32.u64 %0, t; }" : "=r"(a) : "l"(p));
    return a;
}
__device__ __forceinline__ void ldsm4(uint32_t* r, uint32_t addr) {
    asm volatile("ldmatrix.sync.aligned.m8n8.x4.shared.b16 {%0,%1,%2,%3}, [%4];"
                 : "=r"(r[0]), "=r"(r[1]), "=r"(r[2]), "=r"(r[3]) : "r"(addr));
}
__device__ __forceinline__ void mma_bf16(float* c, const uint32_t* a, const uint32_t* b) {
    asm volatile("mma.sync.aligned.m16n8k16.row.col.f32.bf16.bf16.f32 "
                 "{%0,%1,%2,%3}, {%4,%5,%6,%7}, {%8,%9}, {%0,%1,%2,%3};"
                 : "+f"(c[0]), "+f"(c[1]), "+f"(c[2]), "+f"(c[3])
                 : "r"(a[0]), "r"(a[1]), "r"(a[2]), "r"(a[3]), "r"(b[0]), "r"(b[1]));
}

// ---------------- fp32 -> (bf16 hi, bf16 lo) split conversions ----------------
__device__ __forceinline__ void split4(float4 v, __nv_bfloat162* h, __nv_bfloat162* l) {
    float x[4] = {v.x, v.y, v.z, v.w};
    __nv_bfloat16 hh[4], ll[4];
#pragma unroll
    for (int i = 0; i < 4; i++) {
        hh[i] = __float2bfloat16_rn(x[i]);
        ll[i] = __float2bfloat16_rn(x[i] - __bfloat162float(hh[i]));
    }
    h[0] = __nv_bfloat162(hh[0], hh[1]); h[1] = __nv_bfloat162(hh[2], hh[3]);
    l[0] = __nv_bfloat162(ll[0], ll[1]); l[1] = __nv_bfloat162(ll[2], ll[3]);
}

__global__ void conv_split(const float4* __restrict__ src,
                           __nv_bfloat16* __restrict__ hi,
                           __nv_bfloat16* __restrict__ lo, int n4) {
    int i = blockIdx.x * blockDim.x + threadIdx.x;
    if (i >= n4) return;
    __nv_bfloat162 h[2], l[2];
    split4(src[i], h, l);
    ((__nv_bfloat162*)hi)[2 * i] = h[0]; ((__nv_bfloat162*)hi)[2 * i + 1] = h[1];
    ((__nv_bfloat162*)lo)[2 * i] = l[0]; ((__nv_bfloat162*)lo)[2 * i + 1] = l[1];
}

// gather variant: row m of A = token_feats[((m&2047)*16 + (m>>11))*512]
__global__ void conv_split_gather(const float4* __restrict__ tf,
                                  __nv_bfloat16* __restrict__ hi,
                                  __nv_bfloat16* __restrict__ lo) {
    int i = blockIdx.x * blockDim.x + threadIdx.x;
    if (i >= MW * 128) return;
    int m = i >> 7, kq = i & 127;
    float4 v = tf[((size_t)((m & 2047) * 16 + (m >> 11))) * 128 + kq];
    __nv_bfloat162 h[2], l[2];
    split4(v, h, l);
    ((__nv_bfloat162*)hi)[2 * i] = h[0]; ((__nv_bfloat162*)hi)[2 * i + 1] = h[1];
    ((__nv_bfloat162*)lo)[2 * i] = l[0]; ((__nv_bfloat162*)lo)[2 * i + 1] = l[1];
}

// ---------------- HMMA GEMM: C[m][n] = sum_k A[m][k]*B[n][k] + bias[n] ----------------
// K=512. bf16x3 split: hi*hi + hi*lo + lo*hi, fp32 accumulate via mma.sync.
// CTA tile 128x128, BK=64, 8 warps (2m x 4n), warp tile m64 x n32.
// Smem: 2 buffers x 4 planes(Ah,Al,Bh,Bl) x 16KB, XOR-swizzled for ldmatrix.
#define GEMM_SMEM 131072
__global__ void __launch_bounds__(256, 1)
gemm_tc(const __nv_bfloat16* __restrict__ Ahi, const __nv_bfloat16* __restrict__ Alo,
        const __nv_bfloat16* __restrict__ Bhi, const __nv_bfloat16* __restrict__ Blo,
        const float* __restrict__ bias, float* __restrict__ C, int ldc)
{
    extern __shared__ __align__(128) char smg[];
    const uint32_t sb = smem_u32(smg);
    const int tid = threadIdx.x;
    const int lane = tid & 31, wid = tid >> 5;
    const int wm = wid >> 2, wn = wid & 3;
    const int m0 = blockIdx.y * 128, n0 = blockIdx.x * 128;

    const __nv_bfloat16* planes[4] = {
        Ahi + (size_t)m0 * 512, Alo + (size_t)m0 * 512,
        Bhi + (size_t)n0 * 512, Blo + (size_t)n0 * 512 };

    // per-thread ldmatrix row offsets (row&7 == lane&7 for both A and B)
    const int rb = lane & 7;
    const int glA = lane >> 4;          // 0..1
    const int glB = lane >> 3;          // 0..3
    int aoff[4], boff[4];
#pragma unroll
    for (int mt = 0; mt < 4; mt++) {
        int r = wm * 64 + mt * 16 + rb + ((lane >> 3) & 1) * 8;
        aoff[mt] = ((r >> 3) << 10) + (rb << 7);
    }
#pragma unroll
    for (int nt = 0; nt < 4; nt++) {
        int r = wn * 32 + nt * 8 + rb;
        boff[nt] = ((r >> 3) << 10) + (rb << 7);
    }

    float acc[4][4][4];
#pragma unroll
    for (int a = 0; a < 4; a++)
#pragma unroll
        for (int b = 0; b < 4; b++)
#pragma unroll
            for (int d = 0; d < 4; d++) acc[a][b][d] = 0.f;

    const int ldg = tid & 7;            // 16B group within 128B row
    const int ldr = tid >> 3;           // row contribution

    // ---- chunk 0 loads ----
#pragma unroll
    for (int i = 0; i < 16; i++) {
        const int pl = i >> 2;
        const int r = ((i & 3) << 5) + ldr;
        const __nv_bfloat16* src = planes[pl] + (size_t)r * 512 + ldg * 8;
        uint32_t dst = sb + pl * 16384 + ((r >> 3) << 10) + ((r & 7) << 7)
                       + ((ldg ^ (r & 7)) << 4);
        asm volatile("cp.async.cg.shared.global [%0], [%1], 16;" :: "r"(dst), "l"(src));
    }
    asm volatile("cp.async.commit_group;" ::: "memory");

    for (int c = 0; c < 8; c++) {
        asm volatile("cp.async.wait_group 0;" ::: "memory");
        __syncthreads();
        if (c < 7) {
            const int k0 = (c + 1) << 6;
            const uint32_t dbase = sb + ((c + 1) & 1) * 65536;
#pragma unroll
            for (int i = 0; i < 16; i++) {
                const int pl = i >> 2;
                const int r = ((i & 3) << 5) + ldr;
                const __nv_bfloat16* src = planes[pl] + (size_t)r * 512 + k0 + ldg * 8;
                uint32_t dst = dbase + pl * 16384 + ((r >> 3) << 10) + ((r & 7) << 7)
                               + ((ldg ^ (r & 7)) << 4);
                asm volatile("cp.async.cg.shared.global [%0], [%1], 16;" :: "r"(dst), "l"(src));
            }
            asm volatile("cp.async.commit_group;" ::: "memory");
        }

        const uint32_t bbase = sb + (c & 1) * 65536;
        uint32_t Bf[2][4][4];   // [plane][nt][4]: regs 0,1 = step s-even; 2,3 = s-odd
#pragma unroll
        for (int s = 0; s < 4; s++) {
            if ((s & 1) == 0) {
                const int q0 = s << 1;   // groups q0..q0+3 cover two k16 steps
#pragma unroll
                for (int pl = 0; pl < 2; pl++)
#pragma unroll
                    for (int nt = 0; nt < 4; nt++)
                        ldsm4(Bf[pl][nt],
                              bbase + (2 + pl) * 16384 + boff[nt]
                              + (((q0 + glB) ^ rb) << 4));
            }
            uint32_t Af[2][4][4];
#pragma unroll
            for (int pl = 0; pl < 2; pl++)
#pragma unroll
                for (int mt = 0; mt < 4; mt++)
                    ldsm4(Af[pl][mt],
                          bbase + pl * 16384 + aoff[mt]
                          + ((((s << 1) + glA) ^ rb) << 4));
            const int ro = (s & 1) << 1;
#pragma unroll
            for (int mt = 0; mt < 4; mt++)
#pragma unroll
                for (int nt = 0; nt < 4; nt++) {
                    mma_bf16(acc[mt][nt], Af[0][mt], &Bf[0][nt][ro]);  // hi*hi
                    mma_bf16(acc[mt][nt], Af[0][mt], &Bf[1][nt][ro]);  // hi*lo
                    mma_bf16(acc[mt][nt], Af[1][mt], &Bf[0][nt][ro]);  // lo*hi
                }
        }
    }

    // epilogue: bias add + store
    const int rr = lane >> 2, cc = (lane & 3) * 2;
#pragma unroll
    for (int mt = 0; mt < 4; mt++) {
        const int row = m0 + wm * 64 + mt * 16 + rr;
#pragma unroll
        for (int nt = 0; nt < 4; nt++) {
            const int col = n0 + wn * 32 + nt * 8 + cc;
            const float b0 = bias[col], b1 = bias[col + 1];
            float2 v0 = {acc[mt][nt][0] + b0, acc[mt][nt][1] + b1};
            float2 v1 = {acc[mt][nt][2] + b0, acc[mt][nt][3] + b1};
            *(float2*)(C + (size_t)row * ldc + col) = v0;
            *(float2*)(C + (size_t)(row + 8) * ldc + col) = v1;
        }
    }
}

// ---------------- group barrier (8 blocks sharing a (seq-group, dir)) ----------------
__device__ __forceinline__ unsigned ld_acq(const unsigned* p) {
    unsigned v;
    asm volatile("ld.acquire.gpu.u32 %0, [%1];" : "=r"(v) : "l"(p) : "memory");
    return v;
}
__device__ __forceinline__ void group_barrier(unsigned* cnt, unsigned* sense,
                                              unsigned target, int total) {
    __syncthreads();
    if (threadIdx.x == 0) {
        __threadfence();
        unsigned t = atomicAdd(cnt, 1u);
        if (t == (unsigned)(total - 1)) {
            *cnt = 0u;
            asm volatile("red.release.gpu.add.u32 [%0], 1;" :: "l"(sense) : "memory");
        } else {
            while (ld_acq(sense) != target) { }
        }
    }
    __syncthreads();
}

// ---------------- persistent GRU recurrence ----------------
// grid: (8 j-groups, nseq/SPB seq-groups, 2 dirs). 256 thr = 32 jj x 8 sl.
// Dependency group = the 8 j-group blocks sharing (seq-group, dir).
template<int T, int SPB>
__global__ void __launch_bounds__(256, 1)
gru_persistent(const float* __restrict__ xp_base,
               const float* __restrict__ whh_f, const float* __restrict__ whh_b,
               const float* __restrict__ bhh_f, const float* __restrict__ bhh_b,
               float* __restrict__ hbuf,
               float* __restrict__ outbuf,
               unsigned* cnt_arr, unsigned* sense_arr,
               int nseq)
{
    constexpr int NP = SPB / 16;
    extern __shared__ float smf[];
    float* Ws  = smf;
    float* hsm = smf + 96 * 257;
    float* xs  = hsm + 256 * SPB;

    const int tid = threadIdx.x;
    const int jj = tid & 31, sl = tid >> 5;
    const int j0 = blockIdx.x * 32;
    const int sg0 = blockIdx.y * SPB;
    const int dir = blockIdx.z;
    const int gidx = blockIdx.z * gridDim.y + blockIdx.y;
    unsigned* bcnt = cnt_arr + gidx;
    unsigned* bsense = sense_arr + gidx;
    const float* whh = dir ? whh_b : whh_f;
    const float* bhh = dir ? bhh_b : bhh_f;
    const float* xp  = xp_base + (size_t)dir * nseq * T * G3;

    for (int i = tid; i < 96 * 64; i += 256) {
        int r = i >> 6, c = (i & 63) * 4;
        int gate = r >> 5, jr = r & 31;
        float4 v = *(const float4*)(whh + ((size_t)(gate * 256 + j0 + jr)) * 256 + c);
        float* d = Ws + r * 257 + c;
        d[0] = v.x; d[1] = v.y; d[2] = v.z; d[3] = v.w;
    }

    const int j = j0 + jj;
    const float br = bhh[j], bz = bhh[256 + j], bn = bhh[512 + j];
    const unsigned base = ld_acq(bsense);
    __syncthreads();

    for (int step = 0; step < T; step++) {
        const int tt = dir ? (T - 1 - step) : step;
        float xr_[2 * NP], xz_[2 * NP], xn_[2 * NP];
#pragma unroll
        for (int n = 0; n < NP; n++)
#pragma unroll
            for (int e = 0; e < 2; e++) {
                int sL = (sl + n * 8) * 2 + e;
                const float* row = xp + ((size_t)(sg0 + sL) * T + tt) * G3;
                xr_[n * 2 + e] = row[j];
                xz_[n * 2 + e] = row[256 + j];
                xn_[n * 2 + e] = row[512 + j];
            }

        const float* hcur = hbuf + ((size_t)(step & 1) * 2 + dir) * ((size_t)HH * nseq);
        if (step == 0) {
            for (int i = tid; i < 256 * SPB; i += 256) hsm[i] = 0.f;
        } else {
            for (int i = tid; i < 256 * SPB; i += 256) {
                int k = i / SPB, s = i - k * SPB;
                hsm[i] = hcur[(size_t)k * nseq + sg0 + s];
            }
        }
        __syncthreads();

        unsigned long long aR[NP], aZ[NP], aN[NP];
#pragma unroll
        for (int n = 0; n < NP; n++) { aR[n] = 0ULL; aZ[n] = 0ULL; aN[n] = 0ULL; }

        const float* wr = Ws + jj * 257;
        const float* wz = wr + 32 * 257;
        const float* wn = wr + 64 * 257;
#pragma unroll 8
        for (int k = 0; k < 256; k++) {
            unsigned long long r2, z2, n2;
            float fr = wr[k], fz = wz[k], fn = wn[k];
            asm("mov.b64 %0, {%1, %1};" : "=l"(r2) : "f"(fr));
            asm("mov.b64 %0, {%1, %1};" : "=l"(z2) : "f"(fz));
            asm("mov.b64 %0, {%1, %1};" : "=l"(n2) : "f"(fn));
#pragma unroll
            for (int n = 0; n < NP; n++) {
                unsigned long long h2 =
                    *(const unsigned long long*)(hsm + k * SPB + (sl + n * 8) * 2);
                asm("fma.rn.f32x2 %0, %1, %2, %0;" : "+l"(aR[n]) : "l"(r2), "l"(h2));
                asm("fma.rn.f32x2 %0, %1, %2, %0;" : "+l"(aZ[n]) : "l"(z2), "l"(h2));
                asm("fma.rn.f32x2 %0, %1, %2, %0;" : "+l"(aN[n]) : "l"(n2), "l"(h2));
            }
        }

#pragma unroll
        for (int n = 0; n < NP; n++) {
            float rv[2], zv[2], nv[2];
            asm("mov.b64 {%0, %1}, %2;" : "=f"(rv[0]), "=f"(rv[1]) : "l"(aR[n]));
            asm("mov.b64 {%0, %1}, %2;" : "=f"(zv[0]), "=f"(zv[1]) : "l"(aZ[n]));
            asm("mov.b64 {%0, %1}, %2;" : "=f"(nv[0]), "=f"(nv[1]) : "l"(aN[n]));
#pragma unroll
            for (int e = 0; e < 2; e++) {
                int sL = (sl + n * 8) * 2 + e;
                float hold = hsm[(size_t)j * SPB + sL];
                float r  = 1.f / (1.f + expf(-(xr_[n * 2 + e] + rv[e] + br)));
                float z  = 1.f / (1.f + expf(-(xz_[n * 2 + e] + zv[e] + bz)));
                float nn = tanhf(xn_[n * 2 + e] + r * (nv[e] + bn));
                float hnew = (1.f - z) * nn + z * hold;
                xs[jj * (SPB + 1) + sL] = hnew;
                outbuf[((size_t)(sg0 + sL) * T + tt) * HID + dir * HH + j] = hnew;
            }
        }
        __syncthreads();

        float* hnext = hbuf + ((size_t)((step + 1) & 1) * 2 + dir) * ((size_t)HH * nseq);
#pragma unroll
        for (int q = 0; q < 4; q++) {
            int jr = sl * 4 + q;
            if (jj < SPB)
                hnext[(size_t)(j0 + jr) * nseq + sg0 + jj] = xs[jr * (SPB + 1) + jj];
        }

        if (step < T - 1)
            group_barrier(bcnt, bsense, base + (unsigned)step + 1u, 8);
    }
}

// ---------------- attention reduce (unchanged) ----------------
__global__ __launch_bounds__(256)
void attn_reduce(const float* __restrict__ u,
                 const float* __restrict__ feats,
                 const float* __restrict__ ctx,
                 float* __restrict__ dst,
                 int T)
{
    const int seq = blockIdx.x;
    const int tid = threadIdx.x;
    __shared__ float sctx[512];
    __shared__ float ssc[128];
    __shared__ float sred[256];

    for (int g = tid; g < 512; g += 256) sctx[g] = ctx[g];
    __syncthreads();

    const int lane = tid & 31, warp = tid >> 5;
    for (int t = warp; t < T; t += 8) {
        const float* ur = u + ((size_t)seq * T + t) * 512;
        float p = 0.f;
        for (int g = lane; g < 512; g += 32) p += tanhf(ur[g]) * sctx[g];
#pragma unroll
        for (int o = 16; o; o >>= 1) p += __shfl_down_sync(0xffffffffu, p, o);
        if (lane == 0) ssc[t] = p;
    }
    __syncthreads();

    float v = (tid < T) ? ssc[tid] : -1e30f;
    sred[tid] = v; __syncthreads();
    for (int o = 128; o; o >>= 1) { if (tid < o) sred[tid] = fmaxf(sred[tid], sred[tid + o]); __syncthreads(); }
    float mx = sred[0]; __syncthreads();
    float e = (tid < T) ? expf(v - mx) : 0.f;
    sred[tid] = e; __syncthreads();
    for (int o = 128; o; o >>= 1) { if (tid < o) sred[tid] += sred[tid + o]; __syncthreads(); }
    float inv = 1.f / sred[0]; __syncthreads();
    if (tid < T) ssc[tid] = e * inv;
    __syncthreads();

    for (int h = tid; h < 512; h += 256) {
        float acc = 0.f;
        for (int t = 0; t < T; t++)
            acc = fmaf(ssc[t], feats[((size_t)seq * T + t) * 512 + h], acc);
        dst[(size_t)seq * 512 + h] = acc;
    }
}

// ---------------- host ----------------
extern "C" void kernel_launch(void* const* d_in, const int* in_sizes, int n_in,
                              void* d_out, int out_size)
{
    const float* tf       = (const float*)d_in[0];
    const float* w_wih_f  = (const float*)d_in[2];
    const float* w_whh_f  = (const float*)d_in[3];
    const float* w_bih_f  = (const float*)d_in[4];
    const float* w_bhh_f  = (const float*)d_in[5];
    const float* w_wih_b  = (const float*)d_in[6];
    const float* w_whh_b  = (const float*)d_in[7];
    const float* w_bih_b  = (const float*)d_in[8];
    const float* w_bhh_b  = (const float*)d_in[9];
    const float* s_wih_f  = (const float*)d_in[10];
    const float* s_whh_f  = (const float*)d_in[11];
    const float* s_bih_f  = (const float*)d_in[12];
    const float* s_bhh_f  = (const float*)d_in[13];
    const float* s_wih_b  = (const float*)d_in[14];
    const float* s_whh_b  = (const float*)d_in[15];
    const float* s_bih_b  = (const float*)d_in[16];
    const float* s_bhh_b  = (const float*)d_in[17];
    const float* w_attn_w = (const float*)d_in[18];
    const float* w_attn_b = (const float*)d_in[19];
    const float* w_ctx    = (const float*)d_in[20];
    const float* s_attn_w = (const float*)d_in[21];
    const float* s_attn_b = (const float*)d_in[22];
    const float* s_ctx    = (const float*)d_in[23];

    float *xpw, *outw, *uw, *sent, *xps, *outs, *us, *hw, *hs;
    unsigned *bwc, *bws, *bsc, *bss;
    __nv_bfloat16 *Ahi, *Alo, *Whi, *Wlo;
    cudaGetSymbolAddress((void**)&xpw,  g_xpw);
    cudaGetSymbolAddress((void**)&outw, g_outw);
    cudaGetSymbolAddress((void**)&uw,   g_uw);
    cudaGetSymbolAddress((void**)&sent, g_sent);
    cudaGetSymbolAddress((void**)&xps,  g_xps);
    cudaGetSymbolAddress((void**)&outs, g_outs);
    cudaGetSymbolAddress((void**)&us,   g_us);
    cudaGetSymbolAddress((void**)&hw,   g_hw);
    cudaGetSymbolAddress((void**)&hs,   g_hs);
    cudaGetSymbolAddress((void**)&bwc,  g_barw_cnt);
    cudaGetSymbolAddress((void**)&bws,  g_barw_sense);
    cudaGetSymbolAddress((void**)&bsc,  g_bars_cnt);
    cudaGetSymbolAddress((void**)&bss,  g_bars_sense);
    cudaGetSymbolAddress((void**)&Ahi,  g_Ahi);
    cudaGetSymbolAddress((void**)&Alo,  g_Alo);
    cudaGetSymbolAddress((void**)&Whi,  g_Whi);
    cudaGetSymbolAddress((void**)&Wlo,  g_Wlo);

    const size_t smw = (96 * 257 + 256 * 32 + 32 * 33) * sizeof(float);
    const size_t sms = (96 * 257 + 256 * 16 + 32 * 17) * sizeof(float);
    cudaFuncSetAttribute(gru_persistent<LW, 32>,
                         cudaFuncAttributeMaxDynamicSharedMemorySize, (int)smw);
    cudaFuncSetAttribute(gru_persistent<NSENT, 16>,
                         cudaFuncAttributeMaxDynamicSharedMemorySize, (int)sms);
    cudaFuncSetAttribute(gemm_tc,
                         cudaFuncAttributeMaxDynamicSharedMemorySize, GEMM_SMEM);

    // 0) weight splits (6 slots)
    const float* wsrc[6] = {w_wih_f, w_wih_b, w_attn_w, s_wih_f, s_wih_b, s_attn_w};
    const int    wrows[6] = {768, 768, 512, 768, 768, 512};
    for (int i = 0; i < 6; i++) {
        int n4 = wrows[i] * 128;
        conv_split<<<(n4 + 255) / 256, 256>>>((const float4*)wsrc[i],
                                              Whi + (size_t)i * WSLOT,
                                              Wlo + (size_t)i * WSLOT, n4);
    }

    // 1) gather + split token_feats; word input-gate GEMMs on tensor cores
    conv_split_gather<<<(MW * 128 + 255) / 256, 256>>>((const float4*)tf, Ahi, Alo);
    {
        dim3 g(6, 256);
        gemm_tc<<<g, 256, GEMM_SMEM>>>(Ahi, Alo, Whi, Wlo, w_bih_f, xpw, G3);
        gemm_tc<<<g, 256, GEMM_SMEM>>>(Ahi, Alo, Whi + WSLOT, Wlo + WSLOT, w_bih_b,
                                       xpw + (size_t)MW * G3, G3);
    }

    // 2) word BiGRU recurrence (persistent, 16 independent 8-block groups)
    {
        dim3 g(8, NSEQW / 32, 2);
        gru_persistent<LW, 32><<<g, 256, smw>>>(xpw, w_whh_f, w_whh_b, w_bhh_f, w_bhh_b,
                                                hw, outw, bwc, bws, NSEQW);
    }

    // 3) word attention projection (tc) + fused reduce
    conv_split<<<(MW * 128 + 255) / 256, 256>>>((const float4*)outw, Ahi, Alo, MW * 128);
    {
        dim3 g(4, 256);
        gemm_tc<<<g, 256, GEMM_SMEM>>>(Ahi, Alo, Whi + 2 * WSLOT, Wlo + 2 * WSLOT,
                                       w_attn_b, uw, HID);
        attn_reduce<<<NSEQW, 256>>>(uw, outw, w_ctx, sent, LW);
    }

    // 4) sentence input-gate GEMMs (tc)
    conv_split<<<(NSEQW * 128 + 255) / 256, 256>>>((const float4*)sent, Ahi, Alo, NSEQW * 128);
    {
        dim3 g(6, 2);
        gemm_tc<<<g, 256, GEMM_SMEM>>>(Ahi, Alo, Whi + 3 * WSLOT, Wlo + 3 * WSLOT,
                                       s_bih_f, xps, G3);
        gemm_tc<<<g, 256, GEMM_SMEM>>>(Ahi, Alo, Whi + 4 * WSLOT, Wlo + 4 * WSLOT,
                                       s_bih_b, xps + (size_t)BATCH * NSENT * G3, G3);
    }

    // 5) sentence BiGRU (persistent, 2 groups of 8 blocks)
    {
        dim3 g(8, 1, 2);
        gru_persistent<NSENT, 16><<<g, 256, sms>>>(xps, s_whh_f, s_whh_b, s_bhh_f, s_bhh_b,
                                                   hs, outs, bsc, bss, BATCH);
    }

    // 6) sentence attention (tc) -> output
    conv_split<<<(NSEQW * 128 + 255) / 256, 256>>>((const float4*)outs, Ahi, Alo, NSEQW * 128);
    {
        dim3 g(4, 2);
        gemm_tc<<<g, 256, GEMM_SMEM>>>(Ahi, Alo, Whi + 5 * WSLOT, Wlo + 5 * WSLOT,
                                       s_attn_b, us, HID);
        attn_reduce<<<BATCH, 256>>>(us, outs, s_ctx, (float*)d_out, NSENT);
    }
}